// round 3
// baseline (speedup 1.0000x reference)
#include <cuda_runtime.h>

// NoQmix_74560632258885
//
// Algebraic identity (verified R1/R2, rel_err ~1.7e-7): softmax(e, axis=1) is
// normalized over the same axis the final einsum ('bij,bj->b') sums over, so
// Σ_i attention[b,i,j] == 1 for every (b, j). Hence
//   q_tot[b] = Σ_j agent_qs[b,j]
// independent of features, adj, states, W, a.
//
// R3: floor-hypothesis test. R1 (512blk/MLP1) and R2 (64blk/MLP4) both ran
// 4.35-4.38us kernel / 6.1-6.2us total -> duration looks like a fixed
// launch/DVFS floor, not memory time (1MB total). This round: 2 threads/row,
// 8x float4 per thread (128B contiguous, MLP=8), 32 blocks x 256.

__global__ void rowsum64_mlp8_kernel(const float4* __restrict__ qs4,
                                     float* __restrict__ out,
                                     int rows) {
    int t = blockIdx.x * blockDim.x + threadIdx.x;   // global thread id
    int row = t >> 1;                                 // 2 threads per row
    if (row >= rows) return;

    // Thread t owns float4 indices [8t, 8t+7] — 128B contiguous (half a row).
    const float4* p = qs4 + 8 * (long)t;
    float4 v0 = p[0];
    float4 v1 = p[1];
    float4 v2 = p[2];
    float4 v3 = p[3];
    float4 v4 = p[4];
    float4 v5 = p[5];
    float4 v6 = p[6];
    float4 v7 = p[7];

    float s = ((v0.x + v0.y) + (v0.z + v0.w))
            + ((v1.x + v1.y) + (v1.z + v1.w))
            + ((v2.x + v2.y) + (v2.z + v2.w))
            + ((v3.x + v3.y) + (v3.z + v3.w))
            + ((v4.x + v4.y) + (v4.z + v4.w))
            + ((v5.x + v5.y) + (v5.z + v5.w))
            + ((v6.x + v6.y) + (v6.z + v6.w))
            + ((v7.x + v7.y) + (v7.z + v7.w));

    // Pair reduction across the 2 lanes of this row.
    s += __shfl_xor_sync(0xffffffffu, s, 1);

    if ((t & 1) == 0) out[row] = s;
}

extern "C" void kernel_launch(void* const* d_in, const int* in_sizes, int n_in,
                              void* d_out, int out_size) {
    // metadata order: features[0], agent_qs[1], adj[2], states[3], W[4], a[5]
    const float4* agent_qs4 = (const float4*)d_in[1];
    float* out = (float*)d_out;

    int rows = out_size;                 // B = 4096
    int total_threads = rows * 2;        // 2 threads per row
    int threads = 256;
    int blocks = (total_threads + threads - 1) / threads;   // 32

    rowsum64_mlp8_kernel<<<blocks, threads>>>(agent_qs4, out, rows);
}

// round 4
// speedup vs baseline: 1.1036x; 1.1036x over previous
#include <cuda_runtime.h>

// NoQmix_74560632258885
//
// Algebraic identity (verified R1-R3, rel_err ~1.7e-7): softmax(e, axis=1) is
// normalized over the same axis the final einsum ('bij,bj->b') sums over, so
// Σ_i attention[b,i,j] == 1 for every (b, j). Hence
//   q_tot[b] = Σ_j agent_qs[b,j]
// independent of features, adj, states, W, a.
//
// R4: full-chip spread + MLP 2. R3 showed <64 blocks starves SMs (+0.9us);
// R1/R2 showed 64-512 blocks is a plateau. This config: 8 threads/row, each
// thread loads 2 independent float4 (32B contiguous, MLP=2), 128 blocks x 256
// threads (32768 threads, all 148 SMs covered), 3-step shfl reduction.

__global__ void rowsum64_mlp2_kernel(const float4* __restrict__ qs4,
                                     float* __restrict__ out,
                                     int rows) {
    int t = blockIdx.x * blockDim.x + threadIdx.x;   // global thread id
    int row = t >> 3;                                 // 8 threads per row
    if (row >= rows) return;

    // Thread t owns float4 indices [2t, 2t+1] — 32B contiguous, 2 independent
    // LDG.128 in flight.
    const float4* p = qs4 + 2 * t;
    float4 v0 = p[0];
    float4 v1 = p[1];

    float s = ((v0.x + v0.y) + (v0.z + v0.w))
            + ((v1.x + v1.y) + (v1.z + v1.w));

    // Reduce across the 8 lanes of this row (consecutive in-warp).
    s += __shfl_xor_sync(0xffffffffu, s, 4);
    s += __shfl_xor_sync(0xffffffffu, s, 2);
    s += __shfl_xor_sync(0xffffffffu, s, 1);

    if ((t & 7) == 0) out[row] = s;
}

extern "C" void kernel_launch(void* const* d_in, const int* in_sizes, int n_in,
                              void* d_out, int out_size) {
    // metadata order: features[0], agent_qs[1], adj[2], states[3], W[4], a[5]
    const float4* agent_qs4 = (const float4*)d_in[1];
    float* out = (float*)d_out;

    int rows = out_size;                 // B = 4096
    int total_threads = rows * 8;        // 8 threads per row
    int threads = 256;
    int blocks = (total_threads + threads - 1) / threads;   // 128

    rowsum64_mlp2_kernel<<<blocks, threads>>>(agent_qs4, out, rows);
}

// round 5
// speedup vs baseline: 1.1211x; 1.0158x over previous
#include <cuda_runtime.h>

// NoQmix_74560632258885 — FINAL
//
// Algebraic identity (verified R1-R4, rel_err ~1.7e-7): softmax(e, axis=1) is
// normalized over the same axis the final einsum ('bij,bj->b') sums over, so
// Σ_i attention[b,i,j] == 1 for every (b, j) — including fully-masked columns
// (uniform softmax still sums to 1). Hence
//   q_tot[b] = Σ_j agent_qs[b,j]
// independent of features, adj, states, W, a. The 34-GFLOP GAT pipeline in
// the reference is algebraically dead.
//
// Measured design space (total us / ncu kernel us):
//   512blk/MLP1: 6.18/4.35   64blk/MLP4: 6.11/4.38
//   128blk/MLP2: 6.18/4.32   32blk/MLP8: 6.82/5.25  (SM starvation)
// => >=64-block plateau at 6.11-6.18 (one 0.064us timer tick); duration is
// fixed replay/launch overhead + memory-latency floor. Final config: the best
// measured layout (4 threads/row, MLP=4) at 128 CTAs of 128 threads so the
// first wave covers ~all 148 SMs.

__global__ void __launch_bounds__(128)
rowsum64_final_kernel(const float4* __restrict__ qs4,
                      float* __restrict__ out,
                      int rows) {
    int t = blockIdx.x * blockDim.x + threadIdx.x;   // global thread id
    int row = t >> 2;                                 // 4 threads per row
    if (row >= rows) return;

    // Thread t owns float4 indices [4t, 4t+3] — 64B contiguous, 4 independent
    // LDG.128 in flight per thread.
    const float4* p = qs4 + 4 * t;
    float4 v0 = p[0];
    float4 v1 = p[1];
    float4 v2 = p[2];
    float4 v3 = p[3];

    float s = ((v0.x + v0.y) + (v0.z + v0.w))
            + ((v1.x + v1.y) + (v1.z + v1.w))
            + ((v2.x + v2.y) + (v2.z + v2.w))
            + ((v3.x + v3.y) + (v3.z + v3.w));

    // Reduce across the 4 lanes of this row (consecutive in-warp).
    s += __shfl_xor_sync(0xffffffffu, s, 2);
    s += __shfl_xor_sync(0xffffffffu, s, 1);

    if ((t & 3) == 0) out[row] = s;
}

extern "C" void kernel_launch(void* const* d_in, const int* in_sizes, int n_in,
                              void* d_out, int out_size) {
    // metadata order: features[0], agent_qs[1], adj[2], states[3], W[4], a[5]
    const float4* agent_qs4 = (const float4*)d_in[1];
    float* out = (float*)d_out;

    int rows = out_size;                 // B = 4096
    int total_threads = rows * 4;        // 4 threads per row
    int threads = 128;                   // 128 CTAs -> first wave covers chip
    int blocks = (total_threads + threads - 1) / threads;   // 128

    rowsum64_final_kernel<<<blocks, threads>>>(agent_qs4, out, rows);
}